// round 5
// baseline (speedup 1.0000x reference)
#include <cuda_runtime.h>
#include <cuda_bf16.h>
#include <cstdint>

#define B 512
#define HID 128
#define IN_DIM 595

#define TSTR 272            // staged tile row stride (bytes) -> conflict-free ldmatrix
#define TILE_BYTES 34816    // 128 rows * 272

// ---------------- device scratch (no allocations allowed) ----------------
__device__ float g_scratch[4 * B * HID];               // H1, H2, U, V
__device__ __align__(16) unsigned char g_bsw[69632];   // C^T staged: hi[34816], lo[34816]

// ======================= helpers =======================
__device__ __forceinline__ uint32_t smem_u32(const void* p) {
    uint32_t a;
    asm("{ .reg .u64 t; cvta.to.shared.u64 t, %1; cvt.u32.u64 %0, t; }" : "=r"(a) : "l"(p));
    return a;
}
// pack two fp32 -> bf16x2 (lo half = first arg)
__device__ __forceinline__ uint32_t bf2(float lo, float hi) {
    uint32_t r;
    asm("cvt.rn.bf16x2.f32 %0, %1, %2;" : "=r"(r) : "f"(hi), "f"(lo));
    return r;
}
__device__ __forceinline__ void ldm4(uint32_t* r, uint32_t addr) {
    asm volatile("ldmatrix.sync.aligned.m8n8.x4.shared.b16 {%0,%1,%2,%3}, [%4];"
                 : "=r"(r[0]), "=r"(r[1]), "=r"(r[2]), "=r"(r[3]) : "r"(addr));
}
__device__ __forceinline__ void mma_bf16(float* c, const uint32_t* a, uint32_t b0, uint32_t b1) {
    asm volatile(
        "mma.sync.aligned.m16n8k16.row.col.f32.bf16.bf16.f32 "
        "{%0,%1,%2,%3}, {%4,%5,%6,%7}, {%8,%9}, {%0,%1,%2,%3};"
        : "+f"(c[0]), "+f"(c[1]), "+f"(c[2]), "+f"(c[3])
        : "r"(a[0]), "r"(a[1]), "r"(a[2]), "r"(a[3]), "r"(b0), "r"(b1));
}

// ======================= encoder GEMM =======================
// Y[m,n] = act(X[m,:K] @ W[K,128] + bias). 4 rows/block, 512 threads, K split 4 ways.
__global__ __launch_bounds__(512) void enc_gemm(const float* __restrict__ X,
                                                const float* __restrict__ W,
                                                const float* __restrict__ bias,
                                                float* __restrict__ Y, int K, int doRelu) {
    __shared__ float Xs[4 * 608];
    __shared__ float red[3][4][128];
    const int tid = threadIdx.x;
    const int n = tid & 127, q = tid >> 7;
    const int m0 = blockIdx.x * 4;
    for (int idx = tid; idx < 4 * K; idx += 512) {
        int r = idx / K, k = idx - r * K;
        Xs[r * 608 + k] = X[(m0 + r) * K + k];
    }
    __syncthreads();
    const int kb = (K * q) >> 2, ke = (K * (q + 1)) >> 2;
    float a0 = 0.f, a1 = 0.f, a2 = 0.f, a3 = 0.f;
    const float* Wn = W + n;
#pragma unroll 4
    for (int k = kb; k < ke; ++k) {
        float w = __ldg(Wn + k * 128);
        a0 = fmaf(Xs[k], w, a0);
        a1 = fmaf(Xs[608 + k], w, a1);
        a2 = fmaf(Xs[1216 + k], w, a2);
        a3 = fmaf(Xs[1824 + k], w, a3);
    }
    if (q) {
        red[q - 1][0][n] = a0; red[q - 1][1][n] = a1;
        red[q - 1][2][n] = a2; red[q - 1][3][n] = a3;
    }
    __syncthreads();
    if (q == 0) {
        float bv = bias ? bias[n] : 0.f;
        float r0 = a0 + red[0][0][n] + red[1][0][n] + red[2][0][n] + bv;
        float r1 = a1 + red[0][1][n] + red[1][1][n] + red[2][1][n] + bv;
        float r2 = a2 + red[0][2][n] + red[1][2][n] + red[2][2][n] + bv;
        float r3 = a3 + red[0][3][n] + red[1][3][n] + red[2][3][n] + bv;
        if (doRelu) {
            r0 = fmaxf(r0, 0.f); r1 = fmaxf(r1, 0.f);
            r2 = fmaxf(r2, 0.f); r3 = fmaxf(r3, 0.f);
        }
        Y[(m0 + 0) * 128 + n] = r0;
        Y[(m0 + 1) * 128 + n] = r1;
        Y[(m0 + 2) * 128 + n] = r2;
        Y[(m0 + 3) * 128 + n] = r3;
    }
}

// ======================= fused U+V GEMM =======================
// U[m,n] = H2[m,:]@Wp1[0:128,n] + bp1[n];  V[m,n] = H2[m,:]@Wp1[128:256,n].
__global__ __launch_bounds__(512) void enc_uv(const float* __restrict__ H2,
                                              const float* __restrict__ Wp1,
                                              const float* __restrict__ bp1,
                                              float* __restrict__ U, float* __restrict__ V) {
    __shared__ float Xs[512];
    __shared__ float red[3][8][128];
    const int tid = threadIdx.x;
    const int n = tid & 127, q = tid >> 7;
    const int m0 = blockIdx.x * 4;
    Xs[tid] = H2[m0 * 128 + tid];
    __syncthreads();
    float u0 = 0.f, u1 = 0.f, u2 = 0.f, u3 = 0.f;
    float v0 = 0.f, v1 = 0.f, v2 = 0.f, v3 = 0.f;
    const float* Wa = Wp1 + n;
    const float* Wb = Wp1 + 128 * 128 + n;
#pragma unroll 4
    for (int k = q * 32; k < q * 32 + 32; ++k) {
        float wa = __ldg(Wa + k * 128);
        float wb = __ldg(Wb + k * 128);
        float x0 = Xs[k], x1 = Xs[128 + k], x2 = Xs[256 + k], x3 = Xs[384 + k];
        u0 = fmaf(x0, wa, u0); u1 = fmaf(x1, wa, u1);
        u2 = fmaf(x2, wa, u2); u3 = fmaf(x3, wa, u3);
        v0 = fmaf(x0, wb, v0); v1 = fmaf(x1, wb, v1);
        v2 = fmaf(x2, wb, v2); v3 = fmaf(x3, wb, v3);
    }
    if (q) {
        red[q - 1][0][n] = u0; red[q - 1][1][n] = u1;
        red[q - 1][2][n] = u2; red[q - 1][3][n] = u3;
        red[q - 1][4][n] = v0; red[q - 1][5][n] = v1;
        red[q - 1][6][n] = v2; red[q - 1][7][n] = v3;
    }
    __syncthreads();
    if (q == 0) {
        float bv = bp1[n];
        U[(m0 + 0) * 128 + n] = u0 + red[0][0][n] + red[1][0][n] + red[2][0][n] + bv;
        U[(m0 + 1) * 128 + n] = u1 + red[0][1][n] + red[1][1][n] + red[2][1][n] + bv;
        U[(m0 + 2) * 128 + n] = u2 + red[0][2][n] + red[1][2][n] + red[2][2][n] + bv;
        U[(m0 + 3) * 128 + n] = u3 + red[0][3][n] + red[1][3][n] + red[2][3][n] + bv;
        V[(m0 + 0) * 128 + n] = v0 + red[0][4][n] + red[1][4][n] + red[2][4][n];
        V[(m0 + 1) * 128 + n] = v1 + red[0][5][n] + red[1][5][n] + red[2][5][n];
        V[(m0 + 2) * 128 + n] = v2 + red[0][6][n] + red[1][6][n] + red[2][6][n];
        V[(m0 + 3) * 128 + n] = v3 + red[0][7][n] + red[1][7][n] + red[2][7][n];
    }
}

// ======================= prep: C^T hi/lo split, staged layout =======================
__global__ void prep_C(const float* __restrict__ Wp1) {
    int idx = blockIdx.x * 256 + threadIdx.x;   // 16384 total
    int k = idx >> 7, d = idx & 127;
    float v = Wp1[(256 + d) * 128 + k];
    __nv_bfloat16 h = __float2bfloat16_rn(v);
    float lo = v - __bfloat162float(h);
    __nv_bfloat16 l = __float2bfloat16_rn(lo);
    uint32_t off = (uint32_t)k * TSTR + d * 2;
    *(__nv_bfloat16*)(g_bsw + off) = h;
    *(__nv_bfloat16*)(g_bsw + TILE_BYTES + off) = l;
}

// ======================= pairwise kernel (mma.sync bf16, 512 thr) =======================
#define OFF_B   139264
#define OFF_HIS 208896
#define OFF_US  209920
#define OFF_W2  210944
#define OFF_RED 211456
#define SMEM_PAIR 213504

__global__ __launch_bounds__(512, 1) void pair_mma(
    const float* __restrict__ H, const float* __restrict__ U, const float* __restrict__ V,
    const float* __restrict__ Wp2, const float* __restrict__ bp2, float* __restrict__ out) {
    extern __shared__ char sm[];
    const uint32_t sb = smem_u32(sm);
    float* his = (float*)(sm + OFF_HIS);   // [2][128]
    float* Us  = (float*)(sm + OFF_US);    // [2][128]
    float* w2  = (float*)(sm + OFF_W2);    // [128]
    float* red = (float*)(sm + OFF_RED);   // [4][128]

    const int tid  = threadIdx.x;
    const int lane = tid & 31, wid = tid >> 5;
    const int wm = wid & 3, wn = wid >> 2;     // warp tile: 32 j-rows x 32 k-cols
    const int i0 = blockIdx.x * 2;
    const int j0 = blockIdx.y * 128;

    // stage pre-split B (C^T hi+lo, 69632 B = 4352 uint4)
    {
        const uint4* g = (const uint4*)g_bsw;
        uint4* s = (uint4*)(sm + OFF_B);
#pragma unroll
        for (int t = 0; t < 9; ++t) {
            int idx = tid + t * 512;
            if (idx < 4352) s[idx] = g[idx];
        }
    }
    if (tid < 128) {
        his[tid]       = H[i0 * HID + tid];
        his[128 + tid] = H[(i0 + 1) * HID + tid];
        Us[tid]        = U[i0 * HID + tid];
        Us[128 + tid]  = U[(i0 + 1) * HID + tid];
        w2[tid]        = Wp2[tid];
    }
    __syncthreads();

    // build A tiles: A[j][d] = |h_i[d]-h_{j0+j}[d]|, hi/lo split, for both i.
    {
        const int j  = tid >> 2;
        const int dq = (tid & 3) << 5;
        const float4* Hj = (const float4*)(H + (size_t)(j0 + j) * HID + dq);
        const uint32_t offr = (uint32_t)j * TSTR + dq * 2;
#pragma unroll
        for (int t = 0; t < 8; ++t) {
            float4 v = Hj[t];
            const int d = dq + t * 4;
            const uint32_t off = offr + t * 8;
#pragma unroll
            for (int ii = 0; ii < 2; ++ii) {
                const float* hh = his + ii * 128;
                float x0 = fabsf(v.x - hh[d]);
                float x1 = fabsf(v.y - hh[d + 1]);
                float x2 = fabsf(v.z - hh[d + 2]);
                float x3 = fabsf(v.w - hh[d + 3]);
                uint32_t h01 = bf2(x0, x1), h23 = bf2(x2, x3);
                float l0 = x0 - __uint_as_float(h01 << 16);
                float l1 = x1 - __uint_as_float(h01 & 0xffff0000u);
                float l2 = x2 - __uint_as_float(h23 << 16);
                float l3 = x3 - __uint_as_float(h23 & 0xffff0000u);
                uint32_t q01 = bf2(l0, l1), q23 = bf2(l2, l3);
                char* abase = sm + ii * (2 * TILE_BYTES);
                *(uint2*)(abase + off)              = make_uint2(h01, h23);
                *(uint2*)(abase + TILE_BYTES + off) = make_uint2(q01, q23);
            }
        }
    }
    __syncthreads();

    // ldmatrix lane addressing
    const uint32_t aRowOff = (uint32_t)(wm * 32 + (lane & 15)) * TSTR + (lane >> 4) * 16;
    const uint32_t bAddrBase = sb + OFF_B + (uint32_t)(wn * 32 + (lane & 15)) * TSTR + (lane >> 4) * 16;
    const float b2v = bp2[0];

    float acc[2][2][4][4];
#pragma unroll
    for (int ii = 0; ii < 2; ++ii)
#pragma unroll
        for (int a = 0; a < 2; ++a)
#pragma unroll
            for (int b = 0; b < 4; ++b)
#pragma unroll
                for (int c = 0; c < 4; ++c) acc[ii][a][b][c] = 0.f;

#pragma unroll
    for (int ks = 0; ks < 8; ++ks) {
        uint32_t bh[2][4], bl[2][4];
#pragma unroll
        for (int p = 0; p < 2; ++p) {
            ldm4(bh[p], bAddrBase + p * (16 * TSTR) + ks * 32);
            ldm4(bl[p], bAddrBase + TILE_BYTES + p * (16 * TSTR) + ks * 32);
        }
#pragma unroll
        for (int ii = 0; ii < 2; ++ii) {
            const uint32_t aAddrBase = sb + ii * (2 * TILE_BYTES) + aRowOff;
            uint32_t ah[2][4], al[2][4];
#pragma unroll
            for (int mt = 0; mt < 2; ++mt) {
                ldm4(ah[mt], aAddrBase + mt * (16 * TSTR) + ks * 32);
                ldm4(al[mt], aAddrBase + TILE_BYTES + mt * (16 * TSTR) + ks * 32);
            }
#pragma unroll
            for (int mt = 0; mt < 2; ++mt)
#pragma unroll
                for (int nt = 0; nt < 4; ++nt) {
                    uint32_t b0h = bh[nt >> 1][nt & 1], b1h = bh[nt >> 1][(nt & 1) + 2];
                    uint32_t b0l = bl[nt >> 1][nt & 1], b1l = bl[nt >> 1][(nt & 1) + 2];
                    mma_bf16(acc[ii][mt][nt], ah[mt], b0h, b1h);
                    mma_bf16(acc[ii][mt][nt], ah[mt], b0l, b1l);
                    mma_bf16(acc[ii][mt][nt], al[mt], b0h, b1h);
                }
        }
    }

    // epilogue per i: relu(acc + U_i + V_j) . w2, reduce over k
    const int kb = wn * 32;
#pragma unroll
    for (int ii = 0; ii < 2; ++ii) {
#pragma unroll
        for (int mt = 0; mt < 2; ++mt) {
            const int r0 = wm * 32 + mt * 16 + (lane >> 2);
            float p0 = 0.f, p1 = 0.f;
#pragma unroll
            for (int nt = 0; nt < 4; ++nt) {
                const int k = kb + nt * 8 + (lane & 3) * 2;
                float2 v0 = *(const float2*)(V + (size_t)(j0 + r0) * HID + k);
                float2 v1 = *(const float2*)(V + (size_t)(j0 + r0 + 8) * HID + k);
                float u0 = Us[ii * 128 + k], u1 = Us[ii * 128 + k + 1];
                float w0 = w2[k], w1 = w2[k + 1];
                p0 = fmaf(fmaxf(acc[ii][mt][nt][0] + u0 + v0.x, 0.f), w0, p0);
                p0 = fmaf(fmaxf(acc[ii][mt][nt][1] + u1 + v0.y, 0.f), w1, p0);
                p1 = fmaf(fmaxf(acc[ii][mt][nt][2] + u0 + v1.x, 0.f), w0, p1);
                p1 = fmaf(fmaxf(acc[ii][mt][nt][3] + u1 + v1.y, 0.f), w1, p1);
            }
            p0 += __shfl_down_sync(0xffffffffu, p0, 2, 4);
            p0 += __shfl_down_sync(0xffffffffu, p0, 1, 4);
            p1 += __shfl_down_sync(0xffffffffu, p1, 2, 4);
            p1 += __shfl_down_sync(0xffffffffu, p1, 1, 4);
            if ((lane & 3) == 0) {
                red[wn * 128 + r0]     = p0;
                red[wn * 128 + r0 + 8] = p1;
            }
        }
        __syncthreads();
        if (tid < 128) {
            float s = red[tid] + red[128 + tid] + red[256 + tid] + red[384 + tid] + b2v;
            out[(size_t)(i0 + ii) * B + j0 + tid] = s;
        }
        __syncthreads();
    }
}

// ======================= launch =======================
extern "C" void kernel_launch(void* const* d_in, const int* in_sizes, int n_in,
                              void* d_out, int out_size) {
    const float* x   = (const float*)d_in[0];
    const float* W1  = (const float*)d_in[1];
    const float* b1  = (const float*)d_in[2];
    const float* W2  = (const float*)d_in[3];
    const float* b2  = (const float*)d_in[4];
    const float* Wp1 = (const float*)d_in[5];
    const float* bp1 = (const float*)d_in[6];
    const float* Wp2 = (const float*)d_in[7];
    const float* bp2 = (const float*)d_in[8];
    float* out = (float*)d_out;

    float* sp = nullptr;
    cudaGetSymbolAddress((void**)&sp, g_scratch);
    float* H1 = sp;
    float* H2 = sp + B * HID;
    float* U  = sp + 2 * B * HID;
    float* V  = sp + 3 * B * HID;

    prep_C<<<64, 256>>>(Wp1);
    enc_gemm<<<B / 4, 512>>>(x,  W1, b1, H1, IN_DIM, 1);
    enc_gemm<<<B / 4, 512>>>(H1, W2, b2, H2, HID, 1);
    enc_uv<<<B / 4, 512>>>(H2, Wp1, bp1, U, V);

    cudaFuncSetAttribute(pair_mma, cudaFuncAttributeMaxDynamicSharedMemorySize, SMEM_PAIR);
    dim3 grid(B / 2, B / 128);
    pair_mma<<<grid, 512, SMEM_PAIR>>>(H2, U, V, Wp2, bp2, out);
}

// round 6
// speedup vs baseline: 1.1400x; 1.1400x over previous
#include <cuda_runtime.h>
#include <cuda_fp16.h>
#include <cstdint>

#define B 512
#define HID 128
#define IN_DIM 595

#define TSTR 272            // staged tile row stride (bytes) -> conflict-free ldmatrix
#define TILE_BYTES 34816    // 128 rows * 272

// ---------------- device scratch (no allocations allowed) ----------------
__device__ float g_scratch[4 * B * HID];               // H1, H2, U, V
__device__ __align__(16) unsigned char g_bsw[69632];   // C^T staged fp16: hi[34816], lo[34816]

// ======================= helpers =======================
__device__ __forceinline__ uint32_t smem_u32(const void* p) {
    uint32_t a;
    asm("{ .reg .u64 t; cvta.to.shared.u64 t, %1; cvt.u32.u64 %0, t; }" : "=r"(a) : "l"(p));
    return a;
}
// pack two fp32 -> f16x2 (lo half = first arg)
__device__ __forceinline__ uint32_t hf2(float lo, float hi) {
    uint32_t r;
    asm("cvt.rn.f16x2.f32 %0, %1, %2;" : "=r"(r) : "f"(hi), "f"(lo));
    return r;
}
__device__ __forceinline__ void ldm4(uint32_t* r, uint32_t addr) {
    asm volatile("ldmatrix.sync.aligned.m8n8.x4.shared.b16 {%0,%1,%2,%3}, [%4];"
                 : "=r"(r[0]), "=r"(r[1]), "=r"(r[2]), "=r"(r[3]) : "r"(addr));
}
__device__ __forceinline__ void mma_fp16(float* c, const uint32_t* a, uint32_t b0, uint32_t b1) {
    asm volatile(
        "mma.sync.aligned.m16n8k16.row.col.f32.f16.f16.f32 "
        "{%0,%1,%2,%3}, {%4,%5,%6,%7}, {%8,%9}, {%0,%1,%2,%3};"
        : "+f"(c[0]), "+f"(c[1]), "+f"(c[2]), "+f"(c[3])
        : "r"(a[0]), "r"(a[1]), "r"(a[2]), "r"(a[3]), "r"(b0), "r"(b1));
}

// ======================= encoder GEMM =======================
// Y[m,n] = act(X[m,:K] @ W[K,128] + bias). 4 rows/block, 512 threads, K split 4 ways.
__global__ __launch_bounds__(512) void enc_gemm(const float* __restrict__ X,
                                                const float* __restrict__ W,
                                                const float* __restrict__ bias,
                                                float* __restrict__ Y, int K, int doRelu) {
    __shared__ float Xs[4 * 608];
    __shared__ float red[3][4][128];
    const int tid = threadIdx.x;
    const int n = tid & 127, q = tid >> 7;
    const int m0 = blockIdx.x * 4;
    for (int idx = tid; idx < 4 * K; idx += 512) {
        int r = idx / K, k = idx - r * K;
        Xs[r * 608 + k] = X[(m0 + r) * K + k];
    }
    __syncthreads();
    const int kb = (K * q) >> 2, ke = (K * (q + 1)) >> 2;
    float a0 = 0.f, a1 = 0.f, a2 = 0.f, a3 = 0.f;
    const float* Wn = W + n;
#pragma unroll 4
    for (int k = kb; k < ke; ++k) {
        float w = __ldg(Wn + k * 128);
        a0 = fmaf(Xs[k], w, a0);
        a1 = fmaf(Xs[608 + k], w, a1);
        a2 = fmaf(Xs[1216 + k], w, a2);
        a3 = fmaf(Xs[1824 + k], w, a3);
    }
    if (q) {
        red[q - 1][0][n] = a0; red[q - 1][1][n] = a1;
        red[q - 1][2][n] = a2; red[q - 1][3][n] = a3;
    }
    __syncthreads();
    if (q == 0) {
        float bv = bias ? bias[n] : 0.f;
        float r0 = a0 + red[0][0][n] + red[1][0][n] + red[2][0][n] + bv;
        float r1 = a1 + red[0][1][n] + red[1][1][n] + red[2][1][n] + bv;
        float r2 = a2 + red[0][2][n] + red[1][2][n] + red[2][2][n] + bv;
        float r3 = a3 + red[0][3][n] + red[1][3][n] + red[2][3][n] + bv;
        if (doRelu) {
            r0 = fmaxf(r0, 0.f); r1 = fmaxf(r1, 0.f);
            r2 = fmaxf(r2, 0.f); r3 = fmaxf(r3, 0.f);
        }
        Y[(m0 + 0) * 128 + n] = r0;
        Y[(m0 + 1) * 128 + n] = r1;
        Y[(m0 + 2) * 128 + n] = r2;
        Y[(m0 + 3) * 128 + n] = r3;
    }
}

// ======================= prep: C^T fp16 hi/lo split, staged layout =======================
// Bt[k][d] = C[d][k] = Wp1[(256+d)*128 + k], row stride TSTR bytes.
__global__ void prep_C(const float* __restrict__ Wp1) {
    int idx = blockIdx.x * 256 + threadIdx.x;   // 16384 total
    int k = idx >> 7, d = idx & 127;
    float v = Wp1[(256 + d) * 128 + k];
    __half h = __float2half_rn(v);
    float lo = v - __half2float(h);
    __half l = __float2half_rn(lo);
    uint32_t off = (uint32_t)k * TSTR + d * 2;
    *(__half*)(g_bsw + off) = h;
    *(__half*)(g_bsw + TILE_BYTES + off) = l;
}

// ======================= pairwise kernel (mma.sync fp16, occ 2) =======================
// grid (512, 4): blockIdx.x = i, blockIdx.y -> 128-wide j tile.
// D[j,k] = sum_d |h_i[d]-h_j[d]| * C[d,k]; A single fp16, B fp16 hi+lo (2 MMA terms).
// score = relu(D + U_i + V_j) . Wp2 + bp2.
#define OFF_B   34816
#define OFF_HIS 104448
#define OFF_US  104960
#define OFF_W2  105472
#define OFF_RED 105984
#define SMEM_PAIR 108032

__global__ __launch_bounds__(256, 2) void pair_mma(
    const float* __restrict__ H, const float* __restrict__ U, const float* __restrict__ V,
    const float* __restrict__ Wp2, const float* __restrict__ bp2, float* __restrict__ out) {
    extern __shared__ char sm[];
    const uint32_t sb = smem_u32(sm);
    float* his = (float*)(sm + OFF_HIS);   // [128]
    float* Us  = (float*)(sm + OFF_US);    // [128]
    float* w2  = (float*)(sm + OFF_W2);    // [128]
    float* red = (float*)(sm + OFF_RED);   // [4][128]

    const int tid  = threadIdx.x;
    const int lane = tid & 31, wid = tid >> 5;
    const int wm = wid & 1, wn = wid >> 1;     // warp tile: 64 j-rows x 32 k-cols
    const int i  = blockIdx.x;
    const int j0 = blockIdx.y * 128;

    // stage pre-split B (C^T hi+lo fp16, 69632 B = 4352 uint4)
    {
        const uint4* g = (const uint4*)g_bsw;
        uint4* s = (uint4*)(sm + OFF_B);
#pragma unroll
        for (int t = 0; t < 17; ++t) s[tid + t * 256] = g[tid + t * 256];
    }
    if (tid < 128) {
        his[tid] = H[(size_t)i * HID + tid];
        Us[tid]  = U[(size_t)i * HID + tid];
        w2[tid]  = Wp2[tid];
    }
    __syncthreads();

    // build A tile: A[j][d] = fp16(|h_i[d]-h_{j0+j}[d]|)
    {
        const int j  = tid >> 1;
        const int dh = (tid & 1) << 6;
        const float4* Hj = (const float4*)(H + (size_t)(j0 + j) * HID + dh);
        const uint32_t offr = (uint32_t)j * TSTR + dh * 2;
#pragma unroll
        for (int t = 0; t < 16; ++t) {
            float4 v = Hj[t];
            const int d = dh + t * 4;
            float x0 = fabsf(v.x - his[d]);
            float x1 = fabsf(v.y - his[d + 1]);
            float x2 = fabsf(v.z - his[d + 2]);
            float x3 = fabsf(v.w - his[d + 3]);
            *(uint2*)(sm + offr + t * 8) = make_uint2(hf2(x0, x1), hf2(x2, x3));
        }
    }
    __syncthreads();

    // ldmatrix lane addressing (x4: 16 rows, 2 col-halves)
    const uint32_t aAddrBase = sb + (uint32_t)(wm * 64 + (lane & 15)) * TSTR + (lane >> 4) * 16;
    const uint32_t bAddrBase = sb + OFF_B + (uint32_t)(wn * 32 + (lane & 15)) * TSTR + (lane >> 4) * 16;
    const float b2v = bp2[0];

    float acc[4][4][4];
#pragma unroll
    for (int a = 0; a < 4; ++a)
#pragma unroll
        for (int b = 0; b < 4; ++b) {
            acc[a][b][0] = 0.f; acc[a][b][1] = 0.f;
            acc[a][b][2] = 0.f; acc[a][b][3] = 0.f;
        }

#pragma unroll
    for (int ks = 0; ks < 8; ++ks) {
        uint32_t af[4][4], bh[2][4], bl[2][4];
#pragma unroll
        for (int mt = 0; mt < 4; ++mt)
            ldm4(af[mt], aAddrBase + mt * (16 * TSTR) + ks * 32);
#pragma unroll
        for (int p = 0; p < 2; ++p) {
            ldm4(bh[p], bAddrBase + p * (16 * TSTR) + ks * 32);
            ldm4(bl[p], bAddrBase + TILE_BYTES + p * (16 * TSTR) + ks * 32);
        }
#pragma unroll
        for (int mt = 0; mt < 4; ++mt)
#pragma unroll
            for (int nt = 0; nt < 4; ++nt) {
                uint32_t b0h = bh[nt >> 1][nt & 1], b1h = bh[nt >> 1][(nt & 1) + 2];
                uint32_t b0l = bl[nt >> 1][nt & 1], b1l = bl[nt >> 1][(nt & 1) + 2];
                mma_fp16(acc[mt][nt], af[mt], b0h, b1h);
                mma_fp16(acc[mt][nt], af[mt], b0l, b1l);
            }
    }

    // epilogue: relu(acc + U_i + V_j) . w2, reduce over k
    const int kb = wn * 32;
#pragma unroll
    for (int mt = 0; mt < 4; ++mt) {
        const int r0 = wm * 64 + mt * 16 + (lane >> 2);
        float p0 = 0.f, p1 = 0.f;
#pragma unroll
        for (int nt = 0; nt < 4; ++nt) {
            const int k = kb + nt * 8 + (lane & 3) * 2;
            float2 v0 = *(const float2*)(V + (size_t)(j0 + r0) * HID + k);
            float2 v1 = *(const float2*)(V + (size_t)(j0 + r0 + 8) * HID + k);
            float u0 = Us[k], u1 = Us[k + 1];
            float w0 = w2[k], w1 = w2[k + 1];
            p0 = fmaf(fmaxf(acc[mt][nt][0] + u0 + v0.x, 0.f), w0, p0);
            p0 = fmaf(fmaxf(acc[mt][nt][1] + u1 + v0.y, 0.f), w1, p0);
            p1 = fmaf(fmaxf(acc[mt][nt][2] + u0 + v1.x, 0.f), w0, p1);
            p1 = fmaf(fmaxf(acc[mt][nt][3] + u1 + v1.y, 0.f), w1, p1);
        }
        p0 += __shfl_down_sync(0xffffffffu, p0, 2, 4);
        p0 += __shfl_down_sync(0xffffffffu, p0, 1, 4);
        p1 += __shfl_down_sync(0xffffffffu, p1, 2, 4);
        p1 += __shfl_down_sync(0xffffffffu, p1, 1, 4);
        if ((lane & 3) == 0) {
            red[wn * 128 + r0]     = p0;
            red[wn * 128 + r0 + 8] = p1;
        }
    }
    __syncthreads();
    if (tid < 128) {
        float s = red[tid] + red[128 + tid] + red[256 + tid] + red[384 + tid] + b2v;
        out[(size_t)i * B + j0 + tid] = s;
    }
}

// ======================= launch =======================
extern "C" void kernel_launch(void* const* d_in, const int* in_sizes, int n_in,
                              void* d_out, int out_size) {
    const float* x   = (const float*)d_in[0];
    const float* W1  = (const float*)d_in[1];
    const float* b1  = (const float*)d_in[2];
    const float* W2  = (const float*)d_in[3];
    const float* b2  = (const float*)d_in[4];
    const float* Wp1 = (const float*)d_in[5];
    const float* bp1 = (const float*)d_in[6];
    const float* Wp2 = (const float*)d_in[7];
    const float* bp2 = (const float*)d_in[8];
    float* out = (float*)d_out;

    float* sp = nullptr;
    cudaGetSymbolAddress((void**)&sp, g_scratch);
    float* H1 = sp;
    float* H2 = sp + B * HID;
    float* U  = sp + 2 * B * HID;
    float* V  = sp + 3 * B * HID;

    prep_C<<<64, 256>>>(Wp1);
    enc_gemm<<<B / 4, 512>>>(x,  W1, b1, H1, IN_DIM, 1);
    enc_gemm<<<B / 4, 512>>>(H1, W2, b2, H2, HID, 1);
    enc_gemm<<<B / 4, 512>>>(H2, Wp1, bp1, U, HID, 0);
    enc_gemm<<<B / 4, 512>>>(H2, Wp1 + HID * HID, nullptr, V, HID, 0);

    cudaFuncSetAttribute(pair_mma, cudaFuncAttributeMaxDynamicSharedMemorySize, SMEM_PAIR);
    dim3 grid(B, B / 128);
    pair_mma<<<grid, 256, SMEM_PAIR>>>(H2, U, V, Wp2, bp2, out);
}

// round 7
// speedup vs baseline: 1.3748x; 1.2059x over previous
#include <cuda_runtime.h>
#include <cuda_fp16.h>
#include <cstdint>

#define B 512
#define HID 128
#define IN_DIM 595

#define TSTR 272            // A/B tile row stride (bytes) -> conflict-free ldmatrix
#define TILE_BYTES 34816    // 128 rows * 272

// ---------------- device scratch (no allocations allowed) ----------------
__device__ float g_scratch[4 * B * HID];               // H1, H2, U, V
__device__ __align__(16) unsigned char g_bsw[69632];   // C^T staged fp16: hi[34816], lo[34816]

// ======================= helpers =======================
__device__ __forceinline__ uint32_t smem_u32(const void* p) {
    uint32_t a;
    asm("{ .reg .u64 t; cvta.to.shared.u64 t, %1; cvt.u32.u64 %0, t; }" : "=r"(a) : "l"(p));
    return a;
}
__device__ __forceinline__ void ldm4(uint32_t* r, uint32_t addr) {
    asm volatile("ldmatrix.sync.aligned.m8n8.x4.shared.b16 {%0,%1,%2,%3}, [%4];"
                 : "=r"(r[0]), "=r"(r[1]), "=r"(r[2]), "=r"(r[3]) : "r"(addr));
}
__device__ __forceinline__ void mma_fp16(float* c, const uint32_t* a, uint32_t b0, uint32_t b1) {
    asm volatile(
        "mma.sync.aligned.m16n8k16.row.col.f32.f16.f16.f32 "
        "{%0,%1,%2,%3}, {%4,%5,%6,%7}, {%8,%9}, {%0,%1,%2,%3};"
        : "+f"(c[0]), "+f"(c[1]), "+f"(c[2]), "+f"(c[3])
        : "r"(a[0]), "r"(a[1]), "r"(a[2]), "r"(a[3]), "r"(b0), "r"(b1));
}

// ======================= encoder GEMM =======================
// Y[m,n] = act(X[m,:K] @ W[K,128] + bias). 2 rows/block, 512 threads, K split 4 ways.
__global__ __launch_bounds__(512) void enc_gemm(const float* __restrict__ X,
                                                const float* __restrict__ W,
                                                const float* __restrict__ bias,
                                                float* __restrict__ Y, int K, int doRelu) {
    __shared__ float Xs[2 * 608];
    __shared__ float red[3][2][128];
    const int tid = threadIdx.x;
    const int n = tid & 127, q = tid >> 7;
    const int m0 = blockIdx.x * 2;
    for (int idx = tid; idx < 2 * K; idx += 512) {
        int r = idx < K ? 0 : 1, k = idx < K ? idx : idx - K;
        Xs[r * 608 + k] = X[(m0 + r) * K + k];
    }
    __syncthreads();
    const int kb = (K * q) >> 2, ke = (K * (q + 1)) >> 2;
    float a0 = 0.f, a1 = 0.f;
    const float* Wn = W + n;
#pragma unroll 8
    for (int k = kb; k < ke; ++k) {
        float w = __ldg(Wn + k * 128);
        a0 = fmaf(Xs[k], w, a0);
        a1 = fmaf(Xs[608 + k], w, a1);
    }
    if (q) { red[q - 1][0][n] = a0; red[q - 1][1][n] = a1; }
    __syncthreads();
    if (q == 0) {
        float bv = bias ? bias[n] : 0.f;
        float r0 = a0 + red[0][0][n] + red[1][0][n] + red[2][0][n] + bv;
        float r1 = a1 + red[0][1][n] + red[1][1][n] + red[2][1][n] + bv;
        if (doRelu) { r0 = fmaxf(r0, 0.f); r1 = fmaxf(r1, 0.f); }
        Y[(m0 + 0) * 128 + n] = r0;
        Y[(m0 + 1) * 128 + n] = r1;
    }
}

// ======================= prep: C^T fp16 hi/lo split, staged layout =======================
__global__ void prep_C(const float* __restrict__ Wp1) {
    int idx = blockIdx.x * 256 + threadIdx.x;   // 16384 total
    int k = idx >> 7, d = idx & 127;
    float v = Wp1[(256 + d) * 128 + k];
    __half h = __float2half_rn(v);
    float lo = v - __half2float(h);
    __half l = __float2half_rn(lo);
    uint32_t off = (uint32_t)k * TSTR + d * 2;
    *(__half*)(g_bsw + off) = h;
    *(__half*)(g_bsw + TILE_BYTES + off) = l;
}

// ======================= pairwise kernel: 8 i per CTA =======================
// grid (64, 4): blockIdx.x -> 8 consecutive i, blockIdx.y -> 128-wide j tile.
// Staged once per CTA: B (C^T hi/lo fp16), V fp32 tile, his fp16 (8 rows), Us (8 rows).
// Per i: A[j][d] = fp16|h_i - h_j| built from hj registers; 2-term MMA; fused epilogue.
#define OFF_A   0
#define OFF_B   34816
#define OFF_V   104448       // 128 rows * 528 B = 67584
#define VSTR    528
#define OFF_HIS 172032       // 8 * 256 B fp16
#define OFF_US  174080       // 8 * 512 B fp32
#define OFF_W2  178176
#define OFF_RED 178688
#define SMEM_PAIR 180736

__global__ __launch_bounds__(256, 1) void pair_mma(
    const float* __restrict__ H, const float* __restrict__ U, const float* __restrict__ V,
    const float* __restrict__ Wp2, const float* __restrict__ bp2, float* __restrict__ out) {
    extern __shared__ char sm[];
    const uint32_t sb = smem_u32(sm);
    float* w2  = (float*)(sm + OFF_W2);
    float* red = (float*)(sm + OFF_RED);

    const int tid  = threadIdx.x;
    const int lane = tid & 31, wid = tid >> 5;
    const int wm = wid & 1, wn = wid >> 1;     // warp tile: 64 j-rows x 32 k-cols
    const int i_base = blockIdx.x * 8;
    const int j0 = blockIdx.y * 128;

    // ---- stage B (C^T hi+lo fp16, 69632 B = 4352 uint4) ----
    {
        const uint4* g = (const uint4*)g_bsw;
        uint4* s = (uint4*)(sm + OFF_B);
#pragma unroll
        for (int t = 0; t < 17; ++t) s[tid + t * 256] = g[tid + t * 256];
    }
    // ---- per-thread row assignment: j = tid>>1, d-half = 64*(tid&1) ----
    const int j  = tid >> 1;
    const int dh = (tid & 1) << 6;

    // ---- stage V fp32 tile (row stride 528 B) + load hj into registers ----
    __half2 hj2[32];
    {
        const float4* Vg = (const float4*)(V + (size_t)(j0 + j) * HID + dh);
        char* vrow = sm + OFF_V + (uint32_t)j * VSTR + dh * 4;
#pragma unroll
        for (int t = 0; t < 16; ++t) *(float4*)(vrow + t * 16) = Vg[t];
        const float4* Hj = (const float4*)(H + (size_t)(j0 + j) * HID + dh);
#pragma unroll
        for (int t = 0; t < 16; ++t) {
            float4 v = Hj[t];
            hj2[2 * t]     = __floats2half2_rn(v.x, v.y);
            hj2[2 * t + 1] = __floats2half2_rn(v.z, v.w);
        }
    }
    // ---- stage his (fp16) and Us (fp32) for the 8 i's; w2 ----
    if (tid < 128) {
#pragma unroll
        for (int ii = 0; ii < 8; ++ii) {
            float hv = H[(size_t)(i_base + ii) * HID + tid];
            *(__half*)(sm + OFF_HIS + ii * 256 + tid * 2) = __float2half_rn(hv);
            *(float*)(sm + OFF_US + ii * 512 + tid * 4) = U[(size_t)(i_base + ii) * HID + tid];
        }
        w2[tid] = Wp2[tid];
    }
    __syncthreads();

    const uint32_t aAddrBase = sb + OFF_A + (uint32_t)(wm * 64 + (lane & 15)) * TSTR + (lane >> 4) * 16;
    const uint32_t bAddrBase = sb + OFF_B + (uint32_t)(wn * 32 + (lane & 15)) * TSTR + (lane >> 4) * 16;
    const uint32_t aStoreOff = OFF_A + (uint32_t)j * TSTR + dh * 2;
    const float b2v = bp2[0];
    const int kb = wn * 32;

    for (int ii = 0; ii < 8; ++ii) {
        // ---- build A: A[j][d] = |hj - hi| in fp16 (registers -> STS) ----
        {
            const __half2* hi2 = (const __half2*)(sm + OFF_HIS + ii * 256 + dh * 2);
#pragma unroll
            for (int m = 0; m < 8; ++m) {
                __half2 t0 = __habs2(__hsub2(hj2[4 * m + 0], hi2[4 * m + 0]));
                __half2 t1 = __habs2(__hsub2(hj2[4 * m + 1], hi2[4 * m + 1]));
                __half2 t2 = __habs2(__hsub2(hj2[4 * m + 2], hi2[4 * m + 2]));
                __half2 t3 = __habs2(__hsub2(hj2[4 * m + 3], hi2[4 * m + 3]));
                uint4 o;
                o.x = *(uint32_t*)&t0; o.y = *(uint32_t*)&t1;
                o.z = *(uint32_t*)&t2; o.w = *(uint32_t*)&t3;
                *(uint4*)(sm + aStoreOff + m * 16) = o;
            }
        }
        __syncthreads();

        // ---- MMA: A single fp16, B hi+lo (2 terms) ----
        float acc[4][4][4];
#pragma unroll
        for (int a = 0; a < 4; ++a)
#pragma unroll
            for (int b = 0; b < 4; ++b) {
                acc[a][b][0] = 0.f; acc[a][b][1] = 0.f;
                acc[a][b][2] = 0.f; acc[a][b][3] = 0.f;
            }
#pragma unroll
        for (int ks = 0; ks < 8; ++ks) {
            uint32_t af[4][4], bh[2][4], bl[2][4];
#pragma unroll
            for (int mt = 0; mt < 4; ++mt)
                ldm4(af[mt], aAddrBase + mt * (16 * TSTR) + ks * 32);
#pragma unroll
            for (int p = 0; p < 2; ++p) {
                ldm4(bh[p], bAddrBase + p * (16 * TSTR) + ks * 32);
                ldm4(bl[p], bAddrBase + TILE_BYTES + p * (16 * TSTR) + ks * 32);
            }
#pragma unroll
            for (int mt = 0; mt < 4; ++mt)
#pragma unroll
                for (int nt = 0; nt < 4; ++nt) {
                    uint32_t b0h = bh[nt >> 1][nt & 1], b1h = bh[nt >> 1][(nt & 1) + 2];
                    uint32_t b0l = bl[nt >> 1][nt & 1], b1l = bl[nt >> 1][(nt & 1) + 2];
                    mma_fp16(acc[mt][nt], af[mt], b0h, b1h);
                    mma_fp16(acc[mt][nt], af[mt], b0l, b1l);
                }
        }

        // ---- epilogue: relu(acc + U_i + V_j) . w2, reduce over k ----
        const float* Usi = (const float*)(sm + OFF_US + ii * 512);
#pragma unroll
        for (int mt = 0; mt < 4; ++mt) {
            const int r0 = wm * 64 + mt * 16 + (lane >> 2);
            float p0 = 0.f, p1 = 0.f;
#pragma unroll
            for (int nt = 0; nt < 4; ++nt) {
                const int k = kb + nt * 8 + (lane & 3) * 2;
                float2 v0 = *(const float2*)(sm + OFF_V + (uint32_t)r0 * VSTR + k * 4);
                float2 v1 = *(const float2*)(sm + OFF_V + (uint32_t)(r0 + 8) * VSTR + k * 4);
                float u0 = Usi[k], u1 = Usi[k + 1];
                float w0 = w2[k], w1 = w2[k + 1];
                p0 = fmaf(fmaxf(acc[mt][nt][0] + u0 + v0.x, 0.f), w0, p0);
                p0 = fmaf(fmaxf(acc[mt][nt][1] + u1 + v0.y, 0.f), w1, p0);
                p1 = fmaf(fmaxf(acc[mt][nt][2] + u0 + v1.x, 0.f), w0, p1);
                p1 = fmaf(fmaxf(acc[mt][nt][3] + u1 + v1.y, 0.f), w1, p1);
            }
            p0 += __shfl_down_sync(0xffffffffu, p0, 2, 4);
            p0 += __shfl_down_sync(0xffffffffu, p0, 1, 4);
            p1 += __shfl_down_sync(0xffffffffu, p1, 2, 4);
            p1 += __shfl_down_sync(0xffffffffu, p1, 1, 4);
            if ((lane & 3) == 0) {
                red[wn * 128 + r0]     = p0;
                red[wn * 128 + r0 + 8] = p1;
            }
        }
        __syncthreads();
        if (tid < 128) {
            float s = red[tid] + red[128 + tid] + red[256 + tid] + red[384 + tid] + b2v;
            out[(size_t)(i_base + ii) * B + j0 + tid] = s;
        }
        __syncthreads();
    }
}

// ======================= launch =======================
extern "C" void kernel_launch(void* const* d_in, const int* in_sizes, int n_in,
                              void* d_out, int out_size) {
    const float* x   = (const float*)d_in[0];
    const float* W1  = (const float*)d_in[1];
    const float* b1  = (const float*)d_in[2];
    const float* W2  = (const float*)d_in[3];
    const float* b2  = (const float*)d_in[4];
    const float* Wp1 = (const float*)d_in[5];
    const float* bp1 = (const float*)d_in[6];
    const float* Wp2 = (const float*)d_in[7];
    const float* bp2 = (const float*)d_in[8];
    float* out = (float*)d_out;

    float* sp = nullptr;
    cudaGetSymbolAddress((void**)&sp, g_scratch);
    float* H1 = sp;
    float* H2 = sp + B * HID;
    float* U  = sp + 2 * B * HID;
    float* V  = sp + 3 * B * HID;

    prep_C<<<64, 256>>>(Wp1);
    enc_gemm<<<B / 2, 512>>>(x,  W1, b1, H1, IN_DIM, 1);
    enc_gemm<<<B / 2, 512>>>(H1, W2, b2, H2, HID, 1);
    enc_gemm<<<B / 2, 512>>>(H2, Wp1, bp1, U, HID, 0);
    enc_gemm<<<B / 2, 512>>>(H2, Wp1 + HID * HID, nullptr, V, HID, 0);

    cudaFuncSetAttribute(pair_mma, cudaFuncAttributeMaxDynamicSharedMemorySize, SMEM_PAIR);
    dim3 grid(B / 8, B / 128);
    pair_mma<<<grid, 256, SMEM_PAIR>>>(H2, U, V, Wp2, bp2, out);
}

// round 8
// speedup vs baseline: 1.6594x; 1.2070x over previous
#include <cuda_runtime.h>
#include <cuda_fp16.h>
#include <cstdint>

#define B 512
#define HID 128
#define IN_DIM 595

#define TSTR 272            // tile row stride (bytes) -> conflict-free ldmatrix
#define TILE_BYTES 34816    // 128 rows * 272

// ---------------- device scratch (no allocations allowed) ----------------
__device__ float g_scratch[4 * B * HID];               // H1, H2, U, V
__device__ __align__(16) unsigned char g_bsw[34816];   // C^T staged fp16

// ======================= helpers =======================
__device__ __forceinline__ uint32_t smem_u32(const void* p) {
    uint32_t a;
    asm("{ .reg .u64 t; cvta.to.shared.u64 t, %1; cvt.u32.u64 %0, t; }" : "=r"(a) : "l"(p));
    return a;
}
__device__ __forceinline__ void ldm4(uint32_t* r, uint32_t addr) {
    asm volatile("ldmatrix.sync.aligned.m8n8.x4.shared.b16 {%0,%1,%2,%3}, [%4];"
                 : "=r"(r[0]), "=r"(r[1]), "=r"(r[2]), "=r"(r[3]) : "r"(addr));
}
__device__ __forceinline__ void mma_fp16(float* c, const uint32_t* a, uint32_t b0, uint32_t b1) {
    asm volatile(
        "mma.sync.aligned.m16n8k16.row.col.f32.f16.f16.f32 "
        "{%0,%1,%2,%3}, {%4,%5,%6,%7}, {%8,%9}, {%0,%1,%2,%3};"
        : "+f"(c[0]), "+f"(c[1]), "+f"(c[2]), "+f"(c[3])
        : "r"(a[0]), "r"(a[1]), "r"(a[2]), "r"(a[3]), "r"(b0), "r"(b1));
}

// ======================= encoder GEMM (K=595, 2 rows/block) =======================
__global__ __launch_bounds__(512) void enc_gemm(const float* __restrict__ X,
                                                const float* __restrict__ W,
                                                const float* __restrict__ bias,
                                                float* __restrict__ Y, int K, int doRelu) {
    __shared__ float Xs[2 * 608];
    __shared__ float red[3][2][128];
    const int tid = threadIdx.x;
    const int n = tid & 127, q = tid >> 7;
    const int m0 = blockIdx.x * 2;
    for (int idx = tid; idx < 2 * K; idx += 512) {
        int r = idx < K ? 0 : 1, k = idx < K ? idx : idx - K;
        Xs[r * 608 + k] = X[(m0 + r) * K + k];
    }
    __syncthreads();
    const int kb = (K * q) >> 2, ke = (K * (q + 1)) >> 2;
    float a0 = 0.f, a1 = 0.f;
    const float* Wn = W + n;
#pragma unroll 8
    for (int k = kb; k < ke; ++k) {
        float w = __ldg(Wn + k * 128);
        a0 = fmaf(Xs[k], w, a0);
        a1 = fmaf(Xs[608 + k], w, a1);
    }
    if (q) { red[q - 1][0][n] = a0; red[q - 1][1][n] = a1; }
    __syncthreads();
    if (q == 0) {
        float bv = bias ? bias[n] : 0.f;
        float r0 = a0 + red[0][0][n] + red[1][0][n] + red[2][0][n] + bv;
        float r1 = a1 + red[0][1][n] + red[1][1][n] + red[2][1][n] + bv;
        if (doRelu) { r0 = fmaxf(r0, 0.f); r1 = fmaxf(r1, 0.f); }
        Y[(m0 + 0) * 128 + n] = r0;
        Y[(m0 + 1) * 128 + n] = r1;
    }
}

// ======================= encoder GEMM (K=128, 1 row/block) =======================
__global__ __launch_bounds__(512) void enc_gemm1(const float* __restrict__ X,
                                                 const float* __restrict__ W,
                                                 const float* __restrict__ bias,
                                                 float* __restrict__ Y, int doRelu) {
    __shared__ float Xs[128];
    __shared__ float red[3][128];
    const int tid = threadIdx.x;
    const int n = tid & 127, q = tid >> 7;
    const int m = blockIdx.x;
    if (tid < 128) Xs[tid] = X[m * 128 + tid];
    __syncthreads();
    float a = 0.f;
    const float* Wn = W + n;
#pragma unroll 8
    for (int k = q * 32; k < q * 32 + 32; ++k)
        a = fmaf(Xs[k], __ldg(Wn + k * 128), a);
    if (q) red[q - 1][n] = a;
    __syncthreads();
    if (q == 0) {
        float bv = bias ? bias[n] : 0.f;
        float r = a + red[0][n] + red[1][n] + red[2][n] + bv;
        if (doRelu) r = fmaxf(r, 0.f);
        Y[m * 128 + n] = r;
    }
}

// ======================= prep: C^T fp16, staged layout =======================
// Bt[k][d] = C[d][k] = Wp1[(256+d)*128 + k], row stride TSTR bytes.
__global__ void prep_C(const float* __restrict__ Wp1) {
    int idx = blockIdx.x * 256 + threadIdx.x;   // 16384 total
    int k = idx >> 7, d = idx & 127;
    float v = Wp1[(256 + d) * 128 + k];
    *(__half*)(g_bsw + (uint32_t)k * TSTR + d * 2) = __float2half_rn(v);
}

// ======================= pairwise kernel: 8 i per CTA, occ 2 =======================
// grid (64, 4): blockIdx.x -> 8 consecutive i, blockIdx.y -> 128-wide j tile.
// Staged once: B (C^T fp16), HJ (h_j fp16 tile), his fp16, Us fp32, w2.
// Per i: A[j][d] = |hj - hi| fp16 (smem->smem); 1-term MMA; epilogue reads V via L1.
#define OFF_A   0
#define OFF_B   34816
#define OFF_HJ  69632
#define OFF_HIS 104448       // 8 * 256 B fp16
#define OFF_US  106496       // 8 * 512 B fp32
#define OFF_W2  110592
#define OFF_RED 111104
#define SMEM_PAIR 113152

__global__ __launch_bounds__(256, 2) void pair_mma(
    const float* __restrict__ H, const float* __restrict__ U, const float* __restrict__ V,
    const float* __restrict__ Wp2, const float* __restrict__ bp2, float* __restrict__ out) {
    extern __shared__ char sm[];
    const uint32_t sb = smem_u32(sm);
    float* w2  = (float*)(sm + OFF_W2);
    float* red = (float*)(sm + OFF_RED);

    const int tid  = threadIdx.x;
    const int lane = tid & 31, wid = tid >> 5;
    const int wm = wid & 1, wn = wid >> 1;     // warp tile: 64 j-rows x 32 k-cols
    const int i_base = blockIdx.x * 8;
    const int j0 = blockIdx.y * 128;

    // ---- stage B (C^T fp16, 34816 B = 2176 uint4) ----
    {
        const uint4* g = (const uint4*)g_bsw;
        uint4* s = (uint4*)(sm + OFF_B);
#pragma unroll
        for (int t = 0; t < 9; ++t) {
            int idx = tid + t * 256;
            if (idx < 2176) s[idx] = g[idx];
        }
    }
    // ---- per-thread row assignment: j = tid>>1, d-half = 64*(tid&1) ----
    const int j  = tid >> 1;
    const int dh = (tid & 1) << 6;

    // ---- stage HJ: fp16(h_j) tile ----
    {
        const float4* Hj = (const float4*)(H + (size_t)(j0 + j) * HID + dh);
        char* row = sm + OFF_HJ + (uint32_t)j * TSTR + dh * 2;
#pragma unroll
        for (int t = 0; t < 8; ++t) {
            float4 v0 = Hj[2 * t], v1 = Hj[2 * t + 1];
            __half2 a0 = __floats2half2_rn(v0.x, v0.y);
            __half2 a1 = __floats2half2_rn(v0.z, v0.w);
            __half2 a2 = __floats2half2_rn(v1.x, v1.y);
            __half2 a3 = __floats2half2_rn(v1.z, v1.w);
            uint4 o;
            o.x = *(uint32_t*)&a0; o.y = *(uint32_t*)&a1;
            o.z = *(uint32_t*)&a2; o.w = *(uint32_t*)&a3;
            *(uint4*)(row + t * 16) = o;
        }
    }
    // ---- stage his (fp16) and Us (fp32); w2 ----
    if (tid < 128) {
#pragma unroll
        for (int ii = 0; ii < 8; ++ii) {
            float hv = H[(size_t)(i_base + ii) * HID + tid];
            *(__half*)(sm + OFF_HIS + ii * 256 + tid * 2) = __float2half_rn(hv);
            *(float*)(sm + OFF_US + ii * 512 + tid * 4) = U[(size_t)(i_base + ii) * HID + tid];
        }
        w2[tid] = Wp2[tid];
    }
    __syncthreads();

    const uint32_t aAddrBase = sb + OFF_A + (uint32_t)(wm * 64 + (lane & 15)) * TSTR + (lane >> 4) * 16;
    const uint32_t bAddrBase = sb + OFF_B + (uint32_t)(wn * 32 + (lane & 15)) * TSTR + (lane >> 4) * 16;
    const char* hjRow = sm + OFF_HJ + (uint32_t)j * TSTR + dh * 2;
    char* aRow = sm + OFF_A + (uint32_t)j * TSTR + dh * 2;
    const float b2v = bp2[0];
    const int kb = wn * 32;

    for (int ii = 0; ii < 8; ++ii) {
        // ---- build A: A[j][d] = |hj - hi| fp16 ----
        {
            const __half2* hi2 = (const __half2*)(sm + OFF_HIS + ii * 256 + dh * 2);
#pragma unroll
            for (int m = 0; m < 8; ++m) {
                uint4 hv = *(const uint4*)(hjRow + m * 16);
                __half2 j0h = *(__half2*)&hv.x, j1h = *(__half2*)&hv.y;
                __half2 j2h = *(__half2*)&hv.z, j3h = *(__half2*)&hv.w;
                __half2 t0 = __habs2(__hsub2(j0h, hi2[4 * m + 0]));
                __half2 t1 = __habs2(__hsub2(j1h, hi2[4 * m + 1]));
                __half2 t2 = __habs2(__hsub2(j2h, hi2[4 * m + 2]));
                __half2 t3 = __habs2(__hsub2(j3h, hi2[4 * m + 3]));
                uint4 o;
                o.x = *(uint32_t*)&t0; o.y = *(uint32_t*)&t1;
                o.z = *(uint32_t*)&t2; o.w = *(uint32_t*)&t3;
                *(uint4*)(aRow + m * 16) = o;
            }
        }
        __syncthreads();

        // ---- MMA: single-term fp16 ----
        float acc[4][4][4];
#pragma unroll
        for (int a = 0; a < 4; ++a)
#pragma unroll
            for (int b = 0; b < 4; ++b) {
                acc[a][b][0] = 0.f; acc[a][b][1] = 0.f;
                acc[a][b][2] = 0.f; acc[a][b][3] = 0.f;
            }
#pragma unroll
        for (int ks = 0; ks < 8; ++ks) {
            uint32_t af[4][4], bh[2][4];
#pragma unroll
            for (int mt = 0; mt < 4; ++mt)
                ldm4(af[mt], aAddrBase + mt * (16 * TSTR) + ks * 32);
#pragma unroll
            for (int p = 0; p < 2; ++p)
                ldm4(bh[p], bAddrBase + p * (16 * TSTR) + ks * 32);
#pragma unroll
            for (int mt = 0; mt < 4; ++mt)
#pragma unroll
                for (int nt = 0; nt < 4; ++nt)
                    mma_fp16(acc[mt][nt], af[mt],
                             bh[nt >> 1][nt & 1], bh[nt >> 1][(nt & 1) + 2]);
        }

        // ---- epilogue: relu(acc + U_i + V_j) . w2, reduce over k ----
        const float* Usi = (const float*)(sm + OFF_US + ii * 512);
#pragma unroll
        for (int mt = 0; mt < 4; ++mt) {
            const int r0 = wm * 64 + mt * 16 + (lane >> 2);
            float p0 = 0.f, p1 = 0.f;
#pragma unroll
            for (int nt = 0; nt < 4; ++nt) {
                const int k = kb + nt * 8 + (lane & 3) * 2;
                float2 v0 = __ldg((const float2*)(V + (size_t)(j0 + r0) * HID + k));
                float2 v1 = __ldg((const float2*)(V + (size_t)(j0 + r0 + 8) * HID + k));
                float u0 = Usi[k], u1 = Usi[k + 1];
                float w0 = w2[k], w1 = w2[k + 1];
                p0 = fmaf(fmaxf(acc[mt][nt][0] + u0 + v0.x, 0.f), w0, p0);
                p0 = fmaf(fmaxf(acc[mt][nt][1] + u1 + v0.y, 0.f), w1, p0);
                p1 = fmaf(fmaxf(acc[mt][nt][2] + u0 + v1.x, 0.f), w0, p1);
                p1 = fmaf(fmaxf(acc[mt][nt][3] + u1 + v1.y, 0.f), w1, p1);
            }
            p0 += __shfl_down_sync(0xffffffffu, p0, 2, 4);
            p0 += __shfl_down_sync(0xffffffffu, p0, 1, 4);
            p1 += __shfl_down_sync(0xffffffffu, p1, 2, 4);
            p1 += __shfl_down_sync(0xffffffffu, p1, 1, 4);
            if ((lane & 3) == 0) {
                red[wn * 128 + r0]     = p0;
                red[wn * 128 + r0 + 8] = p1;
            }
        }
        __syncthreads();
        if (tid < 128) {
            float s = red[tid] + red[128 + tid] + red[256 + tid] + red[384 + tid] + b2v;
            out[(size_t)(i_base + ii) * B + j0 + tid] = s;
        }
        __syncthreads();
    }
}

// ======================= launch =======================
extern "C" void kernel_launch(void* const* d_in, const int* in_sizes, int n_in,
                              void* d_out, int out_size) {
    const float* x   = (const float*)d_in[0];
    const float* W1  = (const float*)d_in[1];
    const float* b1  = (const float*)d_in[2];
    const float* W2  = (const float*)d_in[3];
    const float* b2  = (const float*)d_in[4];
    const float* Wp1 = (const float*)d_in[5];
    const float* bp1 = (const float*)d_in[6];
    const float* Wp2 = (const float*)d_in[7];
    const float* bp2 = (const float*)d_in[8];
    float* out = (float*)d_out;

    float* sp = nullptr;
    cudaGetSymbolAddress((void**)&sp, g_scratch);
    float* H1 = sp;
    float* H2 = sp + B * HID;
    float* U  = sp + 2 * B * HID;
    float* V  = sp + 3 * B * HID;

    prep_C<<<64, 256>>>(Wp1);
    enc_gemm<<<B / 2, 512>>>(x, W1, b1, H1, IN_DIM, 1);
    enc_gemm1<<<B, 512>>>(H1, W2, b2, H2, 1);
    enc_gemm1<<<B, 512>>>(H2, Wp1, bp1, U, 0);
    enc_gemm1<<<B, 512>>>(H2, Wp1 + HID * HID, nullptr, V, 0);

    cudaFuncSetAttribute(pair_mma, cudaFuncAttributeMaxDynamicSharedMemorySize, SMEM_PAIR);
    dim3 grid(B / 8, B / 128);
    pair_mma<<<grid, 256, SMEM_PAIR>>>(H2, U, V, Wp2, bp2, out);
}